// round 6
// baseline (speedup 1.0000x reference)
#include <cuda_runtime.h>
#include <math.h>
#include <stdint.h>

// Problem constants: B=4, L=2048, HS=2048, NH=32, HD=64, K=16, NM=128, M=B*L=8192

__device__ float g_Q[8192 * 2048];
__device__ float g_K[8192 * 2048];
__device__ float g_V[8192 * 2048];
__device__ float g_Y[8192 * 2048];
__device__ float g_LR[8192 * 32];
__device__ float g_Hr[8192 * 2048];
__device__ float g_Wq[2048 * 2048];
__device__ float g_Wk[2048 * 2048];
__device__ float g_Wv[2048 * 2048];
__device__ float g_Wo[2048 * 2048];

// ---------------------------------------------------------------------------
__device__ __forceinline__ uint32_t f2tf(float x) {
    uint32_t r;
    asm("cvt.rna.tf32.f32 %0, %1;" : "=r"(r) : "f"(x));
    return r;
}

__device__ __forceinline__ void mma_tf32(float* c, const uint32_t* a, const uint32_t* b) {
    asm volatile(
        "mma.sync.aligned.m16n8k8.row.col.f32.tf32.tf32.f32 "
        "{%0,%1,%2,%3}, {%4,%5,%6,%7}, {%8,%9}, {%0,%1,%2,%3};"
        : "+f"(c[0]), "+f"(c[1]), "+f"(c[2]), "+f"(c[3])
        : "r"(a[0]), "r"(a[1]), "r"(a[2]), "r"(a[3]), "r"(b[0]), "r"(b[1]));
}

// ---------------------------------------------------------------------------
// tf32 rounding kernel (float4 elementwise)
// ---------------------------------------------------------------------------
__global__ void round_tf32_kernel(const float* __restrict__ in, float* __restrict__ out, int n4)
{
    int i = blockIdx.x * blockDim.x + threadIdx.x;
    if (i < n4) {
        float4 v = ((const float4*)in)[i];
        v.x = __uint_as_float(f2tf(v.x));
        v.y = __uint_as_float(f2tf(v.y));
        v.z = __uint_as_float(f2tf(v.z));
        v.w = __uint_as_float(f2tf(v.w));
        ((float4*)out)[i] = v;
    }
}

// ---------------------------------------------------------------------------
// TF32 tensor-core GEMM with fragment-ready shared layout.
// C[m,n] = sum_k A[m,k]*W[n,k]; A: MxK row-major, W: NxK row-major, both
// pre-rounded to tf32 values. CTA tile 128x128, BK=16, 256 threads, 8 warps
// each computing 64x32. gridDim.z selects among up to 3 (W, C) pairs.
//
// As frag layout: [(mi*2+ks)*32 + lane][4]  (mi: 8 m16-tiles, ks: 2 k8-slabs)
//   j = hi + 2*half where element = (row mi*16+gid+8*hi, col ks*8+tig+4*half)
// Bs frag layout: [(nj*2+ks)*32 + lane][2]  (nj: 16 n8-tiles)
//   j = half where element = (n nj*8+gid, col ks*8+tig+4*half)
// ---------------------------------------------------------------------------
__global__ __launch_bounds__(256, 2) void gemm_frag(
    const float* __restrict__ A,
    const float* __restrict__ Wa, const float* __restrict__ Wb, const float* __restrict__ Wc,
    float* __restrict__ Ca, float* __restrict__ Cb, float* __restrict__ Cc)
{
    const float* W = (blockIdx.z == 0) ? Wa : (blockIdx.z == 1) ? Wb : Wc;
    float* C = (blockIdx.z == 0) ? Ca : (blockIdx.z == 1) ? Cb : Cc;

    __shared__ __align__(16) float As[2][8 * 2 * 32 * 4];
    __shared__ __align__(16) float Bs[2][16 * 2 * 32 * 2];

    int tid = threadIdx.x;
    int bm = blockIdx.y * 128, bn = blockIdx.x * 128;
    int warp = tid >> 5, lane = tid & 31;
    int wm = (warp & 1) * 64, wn = (warp >> 1) * 32;
    int wmi = (warp & 1) * 4;   // first mi tile
    int wnj = (warp >> 1) * 4;  // first nj tile
    int gid = lane >> 2, tig = lane & 3;

    // loader mapping: thread covers one row, one ks slab (8 cols) of A and of B
    int ar = tid >> 1, ks_l = tid & 1;
    const float* Arow = A + (size_t)(bm + ar) * 2048 + ks_l * 8;
    const float* Wrow = W + (size_t)(bn + ar) * 2048 + ks_l * 8;

    // scatter store bases
    int a_mi = ar >> 4, a_rr = ar & 15, a_gid = a_rr & 7, a_hi = a_rr >> 3;
    int a_base = ((a_mi * 2 + ks_l) * 32 + a_gid * 4) * 4 + a_hi;  // + u*4 + 2*q
    int b_nj = ar >> 3, b_gid = ar & 7;
    int b_base = ((b_nj * 2 + ks_l) * 32 + b_gid * 4) * 2;         // + u*2 + q

    float acc[4][4][4];
#pragma unroll
    for (int mi = 0; mi < 4; mi++)
#pragma unroll
        for (int nj = 0; nj < 4; nj++)
#pragma unroll
            for (int t = 0; t < 4; t++) acc[mi][nj][t] = 0.0f;

    float4 av0 = *(const float4*)(Arow);
    float4 av1 = *(const float4*)(Arow + 4);
    float4 bv0 = *(const float4*)(Wrow);
    float4 bv1 = *(const float4*)(Wrow + 4);

    // store stage 0
    {
        float* Ad = As[0];
        Ad[a_base + 0]      = av0.x; Ad[a_base + 4]      = av0.y;
        Ad[a_base + 8]      = av0.z; Ad[a_base + 12]     = av0.w;
        Ad[a_base + 2]      = av1.x; Ad[a_base + 6]      = av1.y;
        Ad[a_base + 10]     = av1.z; Ad[a_base + 14]     = av1.w;
        float* Bd = Bs[0];
        Bd[b_base + 0] = bv0.x; Bd[b_base + 2] = bv0.y;
        Bd[b_base + 4] = bv0.z; Bd[b_base + 6] = bv0.w;
        Bd[b_base + 1] = bv1.x; Bd[b_base + 3] = bv1.y;
        Bd[b_base + 5] = bv1.z; Bd[b_base + 7] = bv1.w;
    }
    __syncthreads();

    const int NKT = 128;  // 2048 / 16
    for (int kt = 0; kt < NKT; kt++) {
        int cur = kt & 1;
        if (kt + 1 < NKT) {
            int off = (kt + 1) * 16;
            av0 = *(const float4*)(Arow + off);
            av1 = *(const float4*)(Arow + off + 4);
            bv0 = *(const float4*)(Wrow + off);
            bv1 = *(const float4*)(Wrow + off + 4);
        }
#pragma unroll
        for (int ks = 0; ks < 2; ks++) {
            float4 afr[4];
            float2 bfr[4];
#pragma unroll
            for (int mi = 0; mi < 4; mi++)
                afr[mi] = *(const float4*)&As[cur][(((wmi + mi) * 2 + ks) * 32 + lane) * 4];
#pragma unroll
            for (int nj = 0; nj < 4; nj++)
                bfr[nj] = *(const float2*)&Bs[cur][(((wnj + nj) * 2 + ks) * 32 + lane) * 2];
#pragma unroll
            for (int mi = 0; mi < 4; mi++)
#pragma unroll
                for (int nj = 0; nj < 4; nj++)
                    mma_tf32(acc[mi][nj], (const uint32_t*)&afr[mi], (const uint32_t*)&bfr[nj]);
        }
        if (kt + 1 < NKT) {
            int nb = cur ^ 1;
            float* Ad = As[nb];
            Ad[a_base + 0]      = av0.x; Ad[a_base + 4]      = av0.y;
            Ad[a_base + 8]      = av0.z; Ad[a_base + 12]     = av0.w;
            Ad[a_base + 2]      = av1.x; Ad[a_base + 6]      = av1.y;
            Ad[a_base + 10]     = av1.z; Ad[a_base + 14]     = av1.w;
            float* Bd = Bs[nb];
            Bd[b_base + 0] = bv0.x; Bd[b_base + 2] = bv0.y;
            Bd[b_base + 4] = bv0.z; Bd[b_base + 6] = bv0.w;
            Bd[b_base + 1] = bv1.x; Bd[b_base + 3] = bv1.y;
            Bd[b_base + 5] = bv1.z; Bd[b_base + 7] = bv1.w;
        }
        __syncthreads();
    }

    // epilogue
#pragma unroll
    for (int mi = 0; mi < 4; mi++) {
#pragma unroll
        for (int nj = 0; nj < 4; nj++) {
            int row0 = bm + wm + mi * 16 + gid;
            int col = bn + wn + nj * 8 + tig * 2;
            *(float2*)(C + (size_t)row0 * 2048 + col) =
                make_float2(acc[mi][nj][0], acc[mi][nj][1]);
            *(float2*)(C + (size_t)(row0 + 8) * 2048 + col) =
                make_float2(acc[mi][nj][2], acc[mi][nj][3]);
        }
    }
}

// ---------------------------------------------------------------------------
// ttt_lr projection: out[t,h] = dot(H[t,:2048], Wlr[h,:2048]) + lr_bias[h]
// ---------------------------------------------------------------------------
__global__ __launch_bounds__(256) void lr_kernel(
    const float* __restrict__ H, const float* __restrict__ Wlr,
    const float* __restrict__ lr_bias, float* __restrict__ out)
{
    int warp = threadIdx.x >> 5, lane = threadIdx.x & 31;
    int t = blockIdx.x * 8 + warp;
    const float* hrow = H + (size_t)t * 2048;
    float acc[32];
#pragma unroll
    for (int h = 0; h < 32; h++) acc[h] = 0.0f;

    for (int c0 = lane * 4; c0 < 2048; c0 += 128) {
        float4 hv = *(const float4*)(hrow + c0);
#pragma unroll
        for (int h = 0; h < 32; h++) {
            float4 wv = *(const float4*)(Wlr + (size_t)h * 2048 + c0);
            acc[h] += hv.x * wv.x + hv.y * wv.y + hv.z * wv.z + hv.w * wv.w;
        }
    }
#pragma unroll
    for (int h = 0; h < 32; h++) {
        float v = acc[h];
        v += __shfl_xor_sync(0xffffffffu, v, 16);
        v += __shfl_xor_sync(0xffffffffu, v, 8);
        v += __shfl_xor_sync(0xffffffffu, v, 4);
        v += __shfl_xor_sync(0xffffffffu, v, 2);
        v += __shfl_xor_sync(0xffffffffu, v, 1);
        if (lane == h) out[(size_t)t * 32 + h] = v + lr_bias[h];
    }
}

// ---------------------------------------------------------------------------
// Scan kernel: one CTA per (b,h) pair, loops over 128 minibatches.
// ---------------------------------------------------------------------------
__device__ __forceinline__ float rsum16(float v)
{
    v += __shfl_xor_sync(0xffffffffu, v, 1);
    v += __shfl_xor_sync(0xffffffffu, v, 2);
    v += __shfl_xor_sync(0xffffffffu, v, 4);
    v += __shfl_xor_sync(0xffffffffu, v, 8);
    return v;
}

__global__ __launch_bounds__(256, 1) void scan_kernel(
    const float* __restrict__ Q, const float* __restrict__ K_,
    const float* __restrict__ V, const float* __restrict__ LR,
    const float* __restrict__ W1_0, const float* __restrict__ b1_0,
    const float* __restrict__ lnw, const float* __restrict__ lnb,
    const float* __restrict__ ltk, float* __restrict__ Y)
{
    const int SD = 65;
    __shared__ __align__(16) float W1[64 * 64];
    __shared__ float xq[16 * 65], xk[16 * 65], xv[16 * 65], gr[16 * 65];
    __shared__ float b1v[64], gam[64], bet[64];
    __shared__ float coef[256], evec[16], tok[16];

    int bh = blockIdx.x, b = bh >> 5, h = bh & 31;
    int tid = threadIdx.x;

    for (int i = tid; i < 4096; i += 256) W1[i] = W1_0[h * 4096 + i];
    if (tid < 64) {
        b1v[tid] = b1_0[h * 64 + tid];
        gam[tid] = lnw[h * 64 + tid];
        bet[tid] = lnb[h * 64 + tid];
    }
    if (tid < 16) tok[tid] = fmaxf(1.0f / (float)(tid + 1) + ltk[tid], 0.0f);
    __syncthreads();

    int r = tid >> 4;
    int g4 = (tid & 15) << 2;

    for (int nm = 0; nm < 128; nm++) {
        size_t base = ((size_t)b * 2048 + (size_t)nm * 16) * 2048 + (size_t)h * 64;
        for (int i = tid; i < 1024; i += 256) {
            int k = i >> 6, d = i & 63;
            size_t gi = base + (size_t)k * 2048 + d;
            xq[k * SD + d] = Q[gi];
            xk[k * SD + d] = K_[gi];
            xv[k * SD + d] = V[gi];
        }
        if (tid < 16) {
            float x = LR[((size_t)b * 2048 + (size_t)nm * 16 + tid) * 32 + h];
            evec[tid] = (1.0f / (1.0f + expf(-x))) * (1.0f / 64.0f);
        }
        __syncthreads();

        float z[4], qw[4];
#pragma unroll
        for (int t = 0; t < 4; t++) { z[t] = b1v[g4 + t]; qw[t] = b1v[g4 + t]; }
        for (int c = 0; c < 64; c++) {
            float kc = xk[r * SD + c], qc = xq[r * SD + c];
            float4 w4 = *(const float4*)&W1[c * 64 + g4];
            z[0] += kc * w4.x; z[1] += kc * w4.y; z[2] += kc * w4.z; z[3] += kc * w4.w;
            qw[0] += qc * w4.x; qw[1] += qc * w4.y; qw[2] += qc * w4.z; qw[3] += qc * w4.w;
        }

        float s = z[0] + z[1] + z[2] + z[3];
        s = rsum16(s);
        float mu = s * (1.0f / 64.0f);
        float xh[4]; float vs = 0.0f;
#pragma unroll
        for (int t = 0; t < 4; t++) { float d0 = z[t] - mu; xh[t] = d0; vs += d0 * d0; }
        vs = rsum16(vs);
        float rstd = 1.0f / sqrtf(vs * (1.0f / 64.0f) + 1e-6f);
        float gxh[4]; float s1 = 0.0f, s2 = 0.0f;
#pragma unroll
        for (int t = 0; t < 4; t++) {
            xh[t] *= rstd;
            float tgt = xv[r * SD + g4 + t] - xk[r * SD + g4 + t];
            float gm = gam[g4 + t];
            gxh[t] = (gm * xh[t] + bet[g4 + t] - tgt) * gm;
            s1 += gxh[t]; s2 += gxh[t] * xh[t];
        }
        s1 = rsum16(s1);
        s2 = rsum16(s2);
        float c1 = rstd * (1.0f / 64.0f);
#pragma unroll
        for (int t = 0; t < 4; t++)
            gr[r * SD + g4 + t] = (64.0f * gxh[t] - s1 - xh[t] * s2) * c1;
        __syncthreads();

        {
            int i = r, j = tid & 15;
            float a = 0.0f;
            for (int c = 0; c < 64; c++) a += xq[i * SD + c] * xk[j * SD + c];
            coef[i * 16 + j] = (j <= i) ? tok[i] * evec[j] * (1.0f + a) : 0.0f;
        }
        __syncthreads();

        float zb[4] = {qw[0], qw[1], qw[2], qw[3]};
        for (int j = 0; j < 16; j++) {
            float cf = coef[r * 16 + j];
            zb[0] -= cf * gr[j * SD + g4 + 0];
            zb[1] -= cf * gr[j * SD + g4 + 1];
            zb[2] -= cf * gr[j * SD + g4 + 2];
            zb[3] -= cf * gr[j * SD + g4 + 3];
        }
        float s0 = zb[0] + zb[1] + zb[2] + zb[3];
        s0 = rsum16(s0);
        float mu2 = s0 * (1.0f / 64.0f);
        float v2 = 0.0f;
#pragma unroll
        for (int t = 0; t < 4; t++) { float d0 = zb[t] - mu2; v2 += d0 * d0; }
        v2 = rsum16(v2);
        float rstd2 = rsqrtf(v2 * (1.0f / 64.0f) + 1e-6f);
        {
            float o0 = xq[r * SD + g4 + 0] + gam[g4 + 0] * ((zb[0] - mu2) * rstd2) + bet[g4 + 0];
            float o1 = xq[r * SD + g4 + 1] + gam[g4 + 1] * ((zb[1] - mu2) * rstd2) + bet[g4 + 1];
            float o2 = xq[r * SD + g4 + 2] + gam[g4 + 2] * ((zb[2] - mu2) * rstd2) + bet[g4 + 2];
            float o3 = xq[r * SD + g4 + 3] + gam[g4 + 3] * ((zb[3] - mu2) * rstd2) + bet[g4 + 3];
            *(float4*)&Y[base + (size_t)r * 2048 + g4] = make_float4(o0, o1, o2, o3);
        }
        __syncthreads();

        for (int i = tid; i < 1024; i += 256) {
            int j = i >> 6, d = i & 63;
            gr[j * SD + d] *= tok[15] * evec[j];
        }
        __syncthreads();

#pragma unroll
        for (int cc = 0; cc < 4; cc++) {
            int c = r + cc * 16;
            float4* wp = (float4*)&W1[c * 64 + g4];
            float4 w = *wp;
#pragma unroll
            for (int j = 0; j < 16; j++) {
                float xkc = xk[j * SD + c];
                w.x -= xkc * gr[j * SD + g4 + 0];
                w.y -= xkc * gr[j * SD + g4 + 1];
                w.z -= xkc * gr[j * SD + g4 + 2];
                w.w -= xkc * gr[j * SD + g4 + 3];
            }
            *wp = w;
        }
        if (tid < 64) {
            float bb = b1v[tid];
#pragma unroll
            for (int j = 0; j < 16; j++) bb -= gr[j * SD + tid];
            b1v[tid] = bb;
        }
        __syncthreads();
    }
}

// ---------------------------------------------------------------------------
// Post layernorm over HS=2048, in place on Y; output rounded to tf32 values
// (Y then feeds the o-projection GEMM, which assumes pre-rounded input).
// ---------------------------------------------------------------------------
__global__ void postln_kernel(float* __restrict__ Y,
                              const float* __restrict__ w, const float* __restrict__ b)
{
    int t = blockIdx.x;
    float* row = Y + (size_t)t * 2048;
    __shared__ float rs[8], rss[8], mv[2];
    int tid = threadIdx.x;
    float v[8]; float s = 0.0f, ss = 0.0f;
#pragma unroll
    for (int i = 0; i < 8; i++) {
        v[i] = row[tid + i * 256];
        s += v[i]; ss += v[i] * v[i];
    }
#pragma unroll
    for (int m = 16; m >= 1; m >>= 1) {
        s  += __shfl_xor_sync(0xffffffffu, s, m);
        ss += __shfl_xor_sync(0xffffffffu, ss, m);
    }
    if ((tid & 31) == 0) { rs[tid >> 5] = s; rss[tid >> 5] = ss; }
    __syncthreads();
    if (tid == 0) {
        float a = 0.0f, c = 0.0f;
        for (int i = 0; i < 8; i++) { a += rs[i]; c += rss[i]; }
        float mu = a * (1.0f / 2048.0f);
        float var = c * (1.0f / 2048.0f) - mu * mu;
        mv[0] = mu; mv[1] = rsqrtf(var + 1e-6f);
    }
    __syncthreads();
    float mu = mv[0], rstd = mv[1];
#pragma unroll
    for (int i = 0; i < 8; i++) {
        int d = tid + i * 256;
        float o = w[d] * ((v[i] - mu) * rstd) + b[d];
        row[d] = __uint_as_float(f2tf(o));
    }
}

// ---------------------------------------------------------------------------
extern "C" void kernel_launch(void* const* d_in, const int* in_sizes, int n_in,
                              void* d_out, int out_size)
{
    const float* hidden = (const float*)d_in[0];
    const float* q_w  = (const float*)d_in[2];
    const float* k_w  = (const float*)d_in[3];
    const float* v_w  = (const float*)d_in[4];
    const float* o_w  = (const float*)d_in[5];
    const float* W1_0 = (const float*)d_in[6];
    const float* b1_0 = (const float*)d_in[7];
    const float* lnw  = (const float*)d_in[8];
    const float* lnb  = (const float*)d_in[9];
    const float* lr_w = (const float*)d_in[10];
    const float* lr_b = (const float*)d_in[11];
    const float* ltk  = (const float*)d_in[12];
    const float* pnw  = (const float*)d_in[13];
    const float* pnb  = (const float*)d_in[14];
    float* out = (float*)d_out;

    float *Qp, *Kp, *Vp, *Yp, *LRp, *Hr, *Wq, *Wk, *Wv, *Wo;
    cudaGetSymbolAddress((void**)&Qp,  g_Q);
    cudaGetSymbolAddress((void**)&Kp,  g_K);
    cudaGetSymbolAddress((void**)&Vp,  g_V);
    cudaGetSymbolAddress((void**)&Yp,  g_Y);
    cudaGetSymbolAddress((void**)&LRp, g_LR);
    cudaGetSymbolAddress((void**)&Hr,  g_Hr);
    cudaGetSymbolAddress((void**)&Wq,  g_Wq);
    cudaGetSymbolAddress((void**)&Wk,  g_Wk);
    cudaGetSymbolAddress((void**)&Wv,  g_Wv);
    cudaGetSymbolAddress((void**)&Wo,  g_Wo);

    // pre-round all GEMM inputs to tf32 values
    round_tf32_kernel<<<16384, 256>>>(hidden, Hr, 8192 * 2048 / 4);
    round_tf32_kernel<<<4096, 256>>>(q_w, Wq, 2048 * 2048 / 4);
    round_tf32_kernel<<<4096, 256>>>(k_w, Wk, 2048 * 2048 / 4);
    round_tf32_kernel<<<4096, 256>>>(v_w, Wv, 2048 * 2048 / 4);
    round_tf32_kernel<<<4096, 256>>>(o_w, Wo, 2048 * 2048 / 4);

    dim3 gq(16, 64, 3);  // fused Q/K/V
    gemm_frag<<<gq, 256>>>(Hr, Wq, Wk, Wv, Qp, Kp, Vp);
    lr_kernel<<<1024, 256>>>(hidden, lr_w, lr_b, LRp);
    scan_kernel<<<128, 256>>>(Qp, Kp, Vp, LRp, W1_0, b1_0, lnw, lnb, ltk, Yp);
    postln_kernel<<<8192, 256>>>(Yp, pnw, pnb);
    dim3 go(16, 64, 1);
    gemm_frag<<<go, 256>>>(Yp, Wo, Wo, Wo, out, out, out);
}

// round 7
// speedup vs baseline: 1.1222x; 1.1222x over previous
#include <cuda_runtime.h>
#include <math.h>
#include <stdint.h>

// Problem constants: B=4, L=2048, HS=2048, NH=32, HD=64, K=16, NM=128, M=B*L=8192

__device__ float g_Q[8192 * 2048];
__device__ float g_K[8192 * 2048];
__device__ float g_V[8192 * 2048];
__device__ float g_Y[8192 * 2048];
__device__ float g_LR[8192 * 32];
__device__ float g_Hr[8192 * 2048];
__device__ float g_Wq[2048 * 2048];
__device__ float g_Wk[2048 * 2048];
__device__ float g_Wv[2048 * 2048];
__device__ float g_Wo[2048 * 2048];

// ---------------------------------------------------------------------------
__device__ __forceinline__ uint32_t f2tf(float x) {
    uint32_t r;
    asm("cvt.rna.tf32.f32 %0, %1;" : "=r"(r) : "f"(x));
    return r;
}

__device__ __forceinline__ void mma_tf32(float* c, const uint32_t* a, const uint32_t* b) {
    asm volatile(
        "mma.sync.aligned.m16n8k8.row.col.f32.tf32.tf32.f32 "
        "{%0,%1,%2,%3}, {%4,%5,%6,%7}, {%8,%9}, {%0,%1,%2,%3};"
        : "+f"(c[0]), "+f"(c[1]), "+f"(c[2]), "+f"(c[3])
        : "r"(a[0]), "r"(a[1]), "r"(a[2]), "r"(a[3]), "r"(b[0]), "r"(b[1]));
}

// ---------------------------------------------------------------------------
// tf32 rounding kernel (float4 elementwise)
// ---------------------------------------------------------------------------
__global__ void round_tf32_kernel(const float* __restrict__ in, float* __restrict__ out, int n4)
{
    int i = blockIdx.x * blockDim.x + threadIdx.x;
    if (i < n4) {
        float4 v = ((const float4*)in)[i];
        v.x = __uint_as_float(f2tf(v.x));
        v.y = __uint_as_float(f2tf(v.y));
        v.z = __uint_as_float(f2tf(v.z));
        v.w = __uint_as_float(f2tf(v.w));
        ((float4*)out)[i] = v;
    }
}

// ---------------------------------------------------------------------------
// TF32 tensor-core GEMM (round-4 structure): C[m,n] = sum_k A[m,k] * W[n,k]
// A: MxKc row-major, W: NxKc row-major, both pre-rounded to tf32 values.
// 128x128 tile, BK=16, 256 threads. Smem layout [k][m + pad136]:
// fragment loads hit bank = tig*8+gid, all 32 lanes distinct (conflict-free).
// ---------------------------------------------------------------------------
#define GSD 136

__global__ __launch_bounds__(256, 2) void gemm_tf32_nt(
    const float* __restrict__ A, const float* __restrict__ W,
    float* __restrict__ C, int M, int N, int Kc)
{
    __shared__ __align__(16) float As[2][16][GSD];
    __shared__ __align__(16) float Bs[2][16][GSD];

    int tid = threadIdx.x;
    int bm = blockIdx.y * 128, bn = blockIdx.x * 128;
    int warp = tid >> 5, lane = tid & 31;
    int gid = lane >> 2, tig = lane & 3;
    int wm = (warp & 1) * 64, wn = (warp >> 1) * 32;

    // tile loader mapping: thread handles rows jm and jm+64, k-quad jk
    int jm = tid >> 2, jk = (tid & 3) << 2;
    const float* Ar0 = A + (size_t)(bm + jm) * Kc + jk;
    const float* Ar1 = A + (size_t)(bm + jm + 64) * Kc + jk;
    const float* Wr0 = W + (size_t)(bn + jm) * Kc + jk;
    const float* Wr1 = W + (size_t)(bn + jm + 64) * Kc + jk;

    float acc[4][4][4];
#pragma unroll
    for (int mi = 0; mi < 4; mi++)
#pragma unroll
        for (int ni = 0; ni < 4; ni++)
#pragma unroll
            for (int t = 0; t < 4; t++) acc[mi][ni][t] = 0.0f;

    float4 pa0 = *(const float4*)Ar0;
    float4 pa1 = *(const float4*)Ar1;
    float4 pb0 = *(const float4*)Wr0;
    float4 pb1 = *(const float4*)Wr1;

    // store tile 0 (no cvt — inputs pre-rounded)
    As[0][jk + 0][jm] = pa0.x; As[0][jk + 1][jm] = pa0.y;
    As[0][jk + 2][jm] = pa0.z; As[0][jk + 3][jm] = pa0.w;
    As[0][jk + 0][jm + 64] = pa1.x; As[0][jk + 1][jm + 64] = pa1.y;
    As[0][jk + 2][jm + 64] = pa1.z; As[0][jk + 3][jm + 64] = pa1.w;
    Bs[0][jk + 0][jm] = pb0.x; Bs[0][jk + 1][jm] = pb0.y;
    Bs[0][jk + 2][jm] = pb0.z; Bs[0][jk + 3][jm] = pb0.w;
    Bs[0][jk + 0][jm + 64] = pb1.x; Bs[0][jk + 1][jm + 64] = pb1.y;
    Bs[0][jk + 2][jm + 64] = pb1.z; Bs[0][jk + 3][jm + 64] = pb1.w;
    __syncthreads();

    int nk = Kc >> 4;
    for (int kt = 0; kt < nk; kt++) {
        int cur = kt & 1;
        if (kt + 1 < nk) {
            int off = (kt + 1) << 4;
            pa0 = *(const float4*)(Ar0 + off);
            pa1 = *(const float4*)(Ar1 + off);
            pb0 = *(const float4*)(Wr0 + off);
            pb1 = *(const float4*)(Wr1 + off);
        }
#pragma unroll
        for (int ks = 0; ks < 2; ks++) {
            int k8 = ks * 8;
            uint32_t a[4][4], b[4][2];
#pragma unroll
            for (int mi = 0; mi < 4; mi++) {
                int m0 = wm + mi * 16 + gid;
                a[mi][0] = __float_as_uint(As[cur][k8 + tig][m0]);
                a[mi][1] = __float_as_uint(As[cur][k8 + tig][m0 + 8]);
                a[mi][2] = __float_as_uint(As[cur][k8 + tig + 4][m0]);
                a[mi][3] = __float_as_uint(As[cur][k8 + tig + 4][m0 + 8]);
            }
#pragma unroll
            for (int ni = 0; ni < 4; ni++) {
                int n0 = wn + ni * 8 + gid;
                b[ni][0] = __float_as_uint(Bs[cur][k8 + tig][n0]);
                b[ni][1] = __float_as_uint(Bs[cur][k8 + tig + 4][n0]);
            }
#pragma unroll
            for (int mi = 0; mi < 4; mi++)
#pragma unroll
                for (int ni = 0; ni < 4; ni++)
                    mma_tf32(acc[mi][ni], a[mi], b[ni]);
        }
        if (kt + 1 < nk) {
            int nb = cur ^ 1;
            As[nb][jk + 0][jm] = pa0.x; As[nb][jk + 1][jm] = pa0.y;
            As[nb][jk + 2][jm] = pa0.z; As[nb][jk + 3][jm] = pa0.w;
            As[nb][jk + 0][jm + 64] = pa1.x; As[nb][jk + 1][jm + 64] = pa1.y;
            As[nb][jk + 2][jm + 64] = pa1.z; As[nb][jk + 3][jm + 64] = pa1.w;
            Bs[nb][jk + 0][jm] = pb0.x; Bs[nb][jk + 1][jm] = pb0.y;
            Bs[nb][jk + 2][jm] = pb0.z; Bs[nb][jk + 3][jm] = pb0.w;
            Bs[nb][jk + 0][jm + 64] = pb1.x; Bs[nb][jk + 1][jm + 64] = pb1.y;
            Bs[nb][jk + 2][jm + 64] = pb1.z; Bs[nb][jk + 3][jm + 64] = pb1.w;
        }
        __syncthreads();
    }

    // epilogue: c0,c1 at (gid, 2*tig..+1); c2,c3 at (gid+8, ...)
#pragma unroll
    for (int mi = 0; mi < 4; mi++) {
#pragma unroll
        for (int ni = 0; ni < 4; ni++) {
            int row0 = bm + wm + mi * 16 + gid;
            int col = bn + wn + ni * 8 + tig * 2;
            *(float2*)(C + (size_t)row0 * N + col) =
                make_float2(acc[mi][ni][0], acc[mi][ni][1]);
            *(float2*)(C + (size_t)(row0 + 8) * N + col) =
                make_float2(acc[mi][ni][2], acc[mi][ni][3]);
        }
    }
}

// ---------------------------------------------------------------------------
// ttt_lr projection: out[t,h] = dot(H[t,:2048], Wlr[h,:2048]) + lr_bias[h]
// ---------------------------------------------------------------------------
__global__ __launch_bounds__(256) void lr_kernel(
    const float* __restrict__ H, const float* __restrict__ Wlr,
    const float* __restrict__ lr_bias, float* __restrict__ out)
{
    int warp = threadIdx.x >> 5, lane = threadIdx.x & 31;
    int t = blockIdx.x * 8 + warp;
    const float* hrow = H + (size_t)t * 2048;
    float acc[32];
#pragma unroll
    for (int h = 0; h < 32; h++) acc[h] = 0.0f;

    for (int c0 = lane * 4; c0 < 2048; c0 += 128) {
        float4 hv = *(const float4*)(hrow + c0);
#pragma unroll
        for (int h = 0; h < 32; h++) {
            float4 wv = *(const float4*)(Wlr + (size_t)h * 2048 + c0);
            acc[h] += hv.x * wv.x + hv.y * wv.y + hv.z * wv.z + hv.w * wv.w;
        }
    }
#pragma unroll
    for (int h = 0; h < 32; h++) {
        float v = acc[h];
        v += __shfl_xor_sync(0xffffffffu, v, 16);
        v += __shfl_xor_sync(0xffffffffu, v, 8);
        v += __shfl_xor_sync(0xffffffffu, v, 4);
        v += __shfl_xor_sync(0xffffffffu, v, 2);
        v += __shfl_xor_sync(0xffffffffu, v, 1);
        if (lane == h) out[(size_t)t * 32 + h] = v + lr_bias[h];
    }
}

// ---------------------------------------------------------------------------
// Scan kernel: one CTA per (b,h) pair, loops over 128 minibatches.
// ---------------------------------------------------------------------------
__device__ __forceinline__ float rsum16(float v)
{
    v += __shfl_xor_sync(0xffffffffu, v, 1);
    v += __shfl_xor_sync(0xffffffffu, v, 2);
    v += __shfl_xor_sync(0xffffffffu, v, 4);
    v += __shfl_xor_sync(0xffffffffu, v, 8);
    return v;
}

__global__ __launch_bounds__(256, 1) void scan_kernel(
    const float* __restrict__ Q, const float* __restrict__ K_,
    const float* __restrict__ V, const float* __restrict__ LR,
    const float* __restrict__ W1_0, const float* __restrict__ b1_0,
    const float* __restrict__ lnw, const float* __restrict__ lnb,
    const float* __restrict__ ltk, float* __restrict__ Y)
{
    const int SD = 65;
    __shared__ __align__(16) float W1[64 * 64];
    __shared__ float xq[16 * 65], xk[16 * 65], xv[16 * 65], gr[16 * 65];
    __shared__ float b1v[64], gam[64], bet[64];
    __shared__ float coef[256], evec[16], tok[16];

    int bh = blockIdx.x, b = bh >> 5, h = bh & 31;
    int tid = threadIdx.x;

    for (int i = tid; i < 4096; i += 256) W1[i] = W1_0[h * 4096 + i];
    if (tid < 64) {
        b1v[tid] = b1_0[h * 64 + tid];
        gam[tid] = lnw[h * 64 + tid];
        bet[tid] = lnb[h * 64 + tid];
    }
    if (tid < 16) tok[tid] = fmaxf(1.0f / (float)(tid + 1) + ltk[tid], 0.0f);
    __syncthreads();

    int r = tid >> 4;
    int g4 = (tid & 15) << 2;

    for (int nm = 0; nm < 128; nm++) {
        size_t base = ((size_t)b * 2048 + (size_t)nm * 16) * 2048 + (size_t)h * 64;
        for (int i = tid; i < 1024; i += 256) {
            int k = i >> 6, d = i & 63;
            size_t gi = base + (size_t)k * 2048 + d;
            xq[k * SD + d] = Q[gi];
            xk[k * SD + d] = K_[gi];
            xv[k * SD + d] = V[gi];
        }
        if (tid < 16) {
            float x = LR[((size_t)b * 2048 + (size_t)nm * 16 + tid) * 32 + h];
            evec[tid] = (1.0f / (1.0f + expf(-x))) * (1.0f / 64.0f);
        }
        __syncthreads();

        float z[4], qw[4];
#pragma unroll
        for (int t = 0; t < 4; t++) { z[t] = b1v[g4 + t]; qw[t] = b1v[g4 + t]; }
        for (int c = 0; c < 64; c++) {
            float kc = xk[r * SD + c], qc = xq[r * SD + c];
            float4 w4 = *(const float4*)&W1[c * 64 + g4];
            z[0] += kc * w4.x; z[1] += kc * w4.y; z[2] += kc * w4.z; z[3] += kc * w4.w;
            qw[0] += qc * w4.x; qw[1] += qc * w4.y; qw[2] += qc * w4.z; qw[3] += qc * w4.w;
        }

        float s = z[0] + z[1] + z[2] + z[3];
        s = rsum16(s);
        float mu = s * (1.0f / 64.0f);
        float xh[4]; float vs = 0.0f;
#pragma unroll
        for (int t = 0; t < 4; t++) { float d0 = z[t] - mu; xh[t] = d0; vs += d0 * d0; }
        vs = rsum16(vs);
        float rstd = 1.0f / sqrtf(vs * (1.0f / 64.0f) + 1e-6f);
        float gxh[4]; float s1 = 0.0f, s2 = 0.0f;
#pragma unroll
        for (int t = 0; t < 4; t++) {
            xh[t] *= rstd;
            float tgt = xv[r * SD + g4 + t] - xk[r * SD + g4 + t];
            float gm = gam[g4 + t];
            gxh[t] = (gm * xh[t] + bet[g4 + t] - tgt) * gm;
            s1 += gxh[t]; s2 += gxh[t] * xh[t];
        }
        s1 = rsum16(s1);
        s2 = rsum16(s2);
        float c1 = rstd * (1.0f / 64.0f);
#pragma unroll
        for (int t = 0; t < 4; t++)
            gr[r * SD + g4 + t] = (64.0f * gxh[t] - s1 - xh[t] * s2) * c1;
        __syncthreads();

        {
            int i = r, j = tid & 15;
            float a = 0.0f;
            for (int c = 0; c < 64; c++) a += xq[i * SD + c] * xk[j * SD + c];
            coef[i * 16 + j] = (j <= i) ? tok[i] * evec[j] * (1.0f + a) : 0.0f;
        }
        __syncthreads();

        float zb[4] = {qw[0], qw[1], qw[2], qw[3]};
        for (int j = 0; j < 16; j++) {
            float cf = coef[r * 16 + j];
            zb[0] -= cf * gr[j * SD + g4 + 0];
            zb[1] -= cf * gr[j * SD + g4 + 1];
            zb[2] -= cf * gr[j * SD + g4 + 2];
            zb[3] -= cf * gr[j * SD + g4 + 3];
        }
        float s0 = zb[0] + zb[1] + zb[2] + zb[3];
        s0 = rsum16(s0);
        float mu2 = s0 * (1.0f / 64.0f);
        float v2 = 0.0f;
#pragma unroll
        for (int t = 0; t < 4; t++) { float d0 = zb[t] - mu2; v2 += d0 * d0; }
        v2 = rsum16(v2);
        float rstd2 = rsqrtf(v2 * (1.0f / 64.0f) + 1e-6f);
        {
            float o0 = xq[r * SD + g4 + 0] + gam[g4 + 0] * ((zb[0] - mu2) * rstd2) + bet[g4 + 0];
            float o1 = xq[r * SD + g4 + 1] + gam[g4 + 1] * ((zb[1] - mu2) * rstd2) + bet[g4 + 1];
            float o2 = xq[r * SD + g4 + 2] + gam[g4 + 2] * ((zb[2] - mu2) * rstd2) + bet[g4 + 2];
            float o3 = xq[r * SD + g4 + 3] + gam[g4 + 3] * ((zb[3] - mu2) * rstd2) + bet[g4 + 3];
            *(float4*)&Y[base + (size_t)r * 2048 + g4] = make_float4(o0, o1, o2, o3);
        }
        __syncthreads();

        for (int i = tid; i < 1024; i += 256) {
            int j = i >> 6, d = i & 63;
            gr[j * SD + d] *= tok[15] * evec[j];
        }
        __syncthreads();

#pragma unroll
        for (int cc = 0; cc < 4; cc++) {
            int c = r + cc * 16;
            float4* wp = (float4*)&W1[c * 64 + g4];
            float4 w = *wp;
#pragma unroll
            for (int j = 0; j < 16; j++) {
                float xkc = xk[j * SD + c];
                w.x -= xkc * gr[j * SD + g4 + 0];
                w.y -= xkc * gr[j * SD + g4 + 1];
                w.z -= xkc * gr[j * SD + g4 + 2];
                w.w -= xkc * gr[j * SD + g4 + 3];
            }
            *wp = w;
        }
        if (tid < 64) {
            float bb = b1v[tid];
#pragma unroll
            for (int j = 0; j < 16; j++) bb -= gr[j * SD + tid];
            b1v[tid] = bb;
        }
        __syncthreads();
    }
}

// ---------------------------------------------------------------------------
// Post layernorm over HS=2048, in place on Y; output rounded to tf32 values
// (Y then feeds the o-projection GEMM, which assumes pre-rounded input).
// ---------------------------------------------------------------------------
__global__ void postln_kernel(float* __restrict__ Y,
                              const float* __restrict__ w, const float* __restrict__ b)
{
    int t = blockIdx.x;
    float* row = Y + (size_t)t * 2048;
    __shared__ float rs[8], rss[8], mv[2];
    int tid = threadIdx.x;
    float v[8]; float s = 0.0f, ss = 0.0f;
#pragma unroll
    for (int i = 0; i < 8; i++) {
        v[i] = row[tid + i * 256];
        s += v[i]; ss += v[i] * v[i];
    }
#pragma unroll
    for (int m = 16; m >= 1; m >>= 1) {
        s  += __shfl_xor_sync(0xffffffffu, s, m);
        ss += __shfl_xor_sync(0xffffffffu, ss, m);
    }
    if ((tid & 31) == 0) { rs[tid >> 5] = s; rss[tid >> 5] = ss; }
    __syncthreads();
    if (tid == 0) {
        float a = 0.0f, c = 0.0f;
        for (int i = 0; i < 8; i++) { a += rs[i]; c += rss[i]; }
        float mu = a * (1.0f / 2048.0f);
        float var = c * (1.0f / 2048.0f) - mu * mu;
        mv[0] = mu; mv[1] = rsqrtf(var + 1e-6f);
    }
    __syncthreads();
    float mu = mv[0], rstd = mv[1];
#pragma unroll
    for (int i = 0; i < 8; i++) {
        int d = tid + i * 256;
        float o = w[d] * ((v[i] - mu) * rstd) + b[d];
        row[d] = __uint_as_float(f2tf(o));
    }
}

// ---------------------------------------------------------------------------
extern "C" void kernel_launch(void* const* d_in, const int* in_sizes, int n_in,
                              void* d_out, int out_size)
{
    const float* hidden = (const float*)d_in[0];
    const float* q_w  = (const float*)d_in[2];
    const float* k_w  = (const float*)d_in[3];
    const float* v_w  = (const float*)d_in[4];
    const float* o_w  = (const float*)d_in[5];
    const float* W1_0 = (const float*)d_in[6];
    const float* b1_0 = (const float*)d_in[7];
    const float* lnw  = (const float*)d_in[8];
    const float* lnb  = (const float*)d_in[9];
    const float* lr_w = (const float*)d_in[10];
    const float* lr_b = (const float*)d_in[11];
    const float* ltk  = (const float*)d_in[12];
    const float* pnw  = (const float*)d_in[13];
    const float* pnb  = (const float*)d_in[14];
    float* out = (float*)d_out;

    float *Qp, *Kp, *Vp, *Yp, *LRp, *Hr, *Wq, *Wk, *Wv, *Wo;
    cudaGetSymbolAddress((void**)&Qp,  g_Q);
    cudaGetSymbolAddress((void**)&Kp,  g_K);
    cudaGetSymbolAddress((void**)&Vp,  g_V);
    cudaGetSymbolAddress((void**)&Yp,  g_Y);
    cudaGetSymbolAddress((void**)&LRp, g_LR);
    cudaGetSymbolAddress((void**)&Hr,  g_Hr);
    cudaGetSymbolAddress((void**)&Wq,  g_Wq);
    cudaGetSymbolAddress((void**)&Wk,  g_Wk);
    cudaGetSymbolAddress((void**)&Wv,  g_Wv);
    cudaGetSymbolAddress((void**)&Wo,  g_Wo);

    // pre-round all GEMM inputs to tf32 values (bit-identical to in-loop cvt)
    round_tf32_kernel<<<16384, 256>>>(hidden, Hr, 8192 * 2048 / 4);
    round_tf32_kernel<<<4096, 256>>>(q_w, Wq, 2048 * 2048 / 4);
    round_tf32_kernel<<<4096, 256>>>(k_w, Wk, 2048 * 2048 / 4);
    round_tf32_kernel<<<4096, 256>>>(v_w, Wv, 2048 * 2048 / 4);
    round_tf32_kernel<<<4096, 256>>>(o_w, Wo, 2048 * 2048 / 4);

    dim3 gg(2048 / 128, 8192 / 128);
    gemm_tf32_nt<<<gg, 256>>>(Hr, Wq, Qp, 8192, 2048, 2048);
    gemm_tf32_nt<<<gg, 256>>>(Hr, Wk, Kp, 8192, 2048, 2048);
    gemm_tf32_nt<<<gg, 256>>>(Hr, Wv, Vp, 8192, 2048, 2048);
    lr_kernel<<<1024, 256>>>(hidden, lr_w, lr_b, LRp);
    scan_kernel<<<128, 256>>>(Qp, Kp, Vp, LRp, W1_0, b1_0, lnw, lnb, ltk, Yp);
    postln_kernel<<<8192, 256>>>(Yp, pnw, pnb);
    gemm_tf32_nt<<<gg, 256>>>(Yp, Wo, out, 8192, 2048, 2048);
}

// round 8
// speedup vs baseline: 1.2293x; 1.0954x over previous
#include <cuda_runtime.h>
#include <math.h>
#include <stdint.h>

// Problem constants: B=4, L=2048, HS=2048, NH=32, HD=64, K=16, NM=128, M=B*L=8192

__device__ float g_Q[8192 * 2048];
__device__ float g_K[8192 * 2048];
__device__ float g_V[8192 * 2048];
__device__ float g_Y[8192 * 2048];
__device__ float g_LR[8192 * 32];
__device__ float g_Hr[8192 * 2048];
__device__ float g_Wq[2048 * 2048];
__device__ float g_Wk[2048 * 2048];
__device__ float g_Wv[2048 * 2048];
__device__ float g_Wo[2048 * 2048];

// ---------------------------------------------------------------------------
__device__ __forceinline__ uint32_t f2tf(float x) {
    uint32_t r;
    asm("cvt.rna.tf32.f32 %0, %1;" : "=r"(r) : "f"(x));
    return r;
}

__device__ __forceinline__ void mma_tf32(float* c, const uint32_t* a, const uint32_t* b) {
    asm volatile(
        "mma.sync.aligned.m16n8k8.row.col.f32.tf32.tf32.f32 "
        "{%0,%1,%2,%3}, {%4,%5,%6,%7}, {%8,%9}, {%0,%1,%2,%3};"
        : "+f"(c[0]), "+f"(c[1]), "+f"(c[2]), "+f"(c[3])
        : "r"(a[0]), "r"(a[1]), "r"(a[2]), "r"(a[3]), "r"(b[0]), "r"(b[1]));
}

__device__ __forceinline__ uint32_t smem_u32(const void* p) {
    uint32_t a;
    asm("{ .reg .u64 t; cvta.to.shared.u64 t, %1; cvt.u32.u64 %0, t; }" : "=r"(a) : "l"(p));
    return a;
}

__device__ __forceinline__ void cp16(uint32_t s, const float* g) {
    asm volatile("cp.async.cg.shared.global [%0], [%1], 16;" :: "r"(s), "l"(g));
}
#define CP_COMMIT() asm volatile("cp.async.commit_group;" ::: "memory")
#define CP_WAIT1()  asm volatile("cp.async.wait_group 1;" ::: "memory")
#define CP_WAIT0()  asm volatile("cp.async.wait_group 0;" ::: "memory")

// ---------------------------------------------------------------------------
// tf32 rounding kernel (float4 elementwise)
// ---------------------------------------------------------------------------
__global__ void round_tf32_kernel(const float* __restrict__ in, float* __restrict__ out, int n4)
{
    int i = blockIdx.x * blockDim.x + threadIdx.x;
    if (i < n4) {
        float4 v = ((const float4*)in)[i];
        v.x = __uint_as_float(f2tf(v.x));
        v.y = __uint_as_float(f2tf(v.y));
        v.z = __uint_as_float(f2tf(v.z));
        v.w = __uint_as_float(f2tf(v.w));
        ((float4*)out)[i] = v;
    }
}

// ---------------------------------------------------------------------------
// TF32 tensor-core GEMM, 3-stage cp.async pipeline.
// C[m,n] = sum_k A[m,k]*W[n,k]; A: 8192x2048 row-major, W: 2048x2048 row-major,
// both pre-rounded to tf32 values. 128x128 CTA tile, BK=16, 256 threads.
// Smem [m][k] layout, row stride 20 floats: fragment LDS bank =
// (20*gid + tig (+4) (+8)) mod 32 — all 32 lanes distinct, conflict-free.
// ---------------------------------------------------------------------------
#define ST 20            // smem row stride (floats)
#define TILE_F (128 * ST) // floats per tile buffer
#define GEMM_SMEM (6 * TILE_F * 4)  // 3 stages x (A+B) = 61440 bytes

__global__ __launch_bounds__(256, 2) void gemm_tf32_nt(
    const float* __restrict__ A, const float* __restrict__ W,
    float* __restrict__ C)
{
    extern __shared__ __align__(16) float smem[];
    float* As = smem;                 // [3][TILE_F]
    float* Bs = smem + 3 * TILE_F;    // [3][TILE_F]

    int tid = threadIdx.x;
    int bm = blockIdx.y * 128, bn = blockIdx.x * 128;
    int warp = tid >> 5, lane = tid & 31;
    int gid = lane >> 2, tig = lane & 3;
    int wm = (warp & 1) * 64, wn = (warp >> 1) * 32;

    // loader mapping: thread -> row tid>>1, k-chunk pair (tid&1)*8 .. +8
    int lrow = tid >> 1, lk = (tid & 1) * 8;
    const float* Ag = A + (size_t)(bm + lrow) * 2048 + lk;
    const float* Wg = W + (size_t)(bn + lrow) * 2048 + lk;
    uint32_t As_s = smem_u32(As) + (lrow * ST + lk) * 4;
    uint32_t Bs_s = smem_u32(Bs) + (lrow * ST + lk) * 4;

    float acc[4][4][4];
#pragma unroll
    for (int mi = 0; mi < 4; mi++)
#pragma unroll
        for (int ni = 0; ni < 4; ni++)
#pragma unroll
            for (int t = 0; t < 4; t++) acc[mi][ni][t] = 0.0f;

    // prologue: issue loads for stages 0 and 1
#pragma unroll
    for (int s = 0; s < 2; s++) {
        uint32_t ao = As_s + s * TILE_F * 4;
        uint32_t bo = Bs_s + s * TILE_F * 4;
        const float* ag = Ag + s * 16;
        const float* wg = Wg + s * 16;
        cp16(ao, ag); cp16(ao + 16, ag + 4);
        cp16(bo, wg); cp16(bo + 16, wg + 4);
        CP_COMMIT();
    }

    const int NKT = 128;
    for (int kt = 0; kt < NKT; kt++) {
        CP_WAIT1();
        __syncthreads();

        // issue load for stage kt+2 (its buffer was consumed at kt-1)
        if (kt + 2 < NKT) {
            int s = (kt + 2) % 3;
            uint32_t ao = As_s + s * TILE_F * 4;
            uint32_t bo = Bs_s + s * TILE_F * 4;
            const float* ag = Ag + (kt + 2) * 16;
            const float* wg = Wg + (kt + 2) * 16;
            cp16(ao, ag); cp16(ao + 16, ag + 4);
            cp16(bo, wg); cp16(bo + 16, wg + 4);
        }
        CP_COMMIT();  // commit even if empty to keep group accounting uniform

        const float* Ab = As + (kt % 3) * TILE_F;
        const float* Bb = Bs + (kt % 3) * TILE_F;
#pragma unroll
        for (int ks = 0; ks < 2; ks++) {
            int k8 = ks * 8;
            uint32_t a[4][4], b[4][2];
#pragma unroll
            for (int mi = 0; mi < 4; mi++) {
                int m0 = wm + mi * 16 + gid;
                a[mi][0] = __float_as_uint(Ab[m0 * ST + k8 + tig]);
                a[mi][1] = __float_as_uint(Ab[(m0 + 8) * ST + k8 + tig]);
                a[mi][2] = __float_as_uint(Ab[m0 * ST + k8 + tig + 4]);
                a[mi][3] = __float_as_uint(Ab[(m0 + 8) * ST + k8 + tig + 4]);
            }
#pragma unroll
            for (int ni = 0; ni < 4; ni++) {
                int n0 = wn + ni * 8 + gid;
                b[ni][0] = __float_as_uint(Bb[n0 * ST + k8 + tig]);
                b[ni][1] = __float_as_uint(Bb[n0 * ST + k8 + tig + 4]);
            }
#pragma unroll
            for (int mi = 0; mi < 4; mi++)
#pragma unroll
                for (int ni = 0; ni < 4; ni++)
                    mma_tf32(acc[mi][ni], a[mi], b[ni]);
        }
    }

    // epilogue
#pragma unroll
    for (int mi = 0; mi < 4; mi++) {
#pragma unroll
        for (int ni = 0; ni < 4; ni++) {
            int row0 = bm + wm + mi * 16 + gid;
            int col = bn + wn + ni * 8 + tig * 2;
            *(float2*)(C + (size_t)row0 * 2048 + col) =
                make_float2(acc[mi][ni][0], acc[mi][ni][1]);
            *(float2*)(C + (size_t)(row0 + 8) * 2048 + col) =
                make_float2(acc[mi][ni][2], acc[mi][ni][3]);
        }
    }
}

// ---------------------------------------------------------------------------
// ttt_lr projection: out[t,h] = dot(H[t,:2048], Wlr[h,:2048]) + lr_bias[h]
// ---------------------------------------------------------------------------
__global__ __launch_bounds__(256) void lr_kernel(
    const float* __restrict__ H, const float* __restrict__ Wlr,
    const float* __restrict__ lr_bias, float* __restrict__ out)
{
    int warp = threadIdx.x >> 5, lane = threadIdx.x & 31;
    int t = blockIdx.x * 8 + warp;
    const float* hrow = H + (size_t)t * 2048;
    float acc[32];
#pragma unroll
    for (int h = 0; h < 32; h++) acc[h] = 0.0f;

    for (int c0 = lane * 4; c0 < 2048; c0 += 128) {
        float4 hv = *(const float4*)(hrow + c0);
#pragma unroll
        for (int h = 0; h < 32; h++) {
            float4 wv = *(const float4*)(Wlr + (size_t)h * 2048 + c0);
            acc[h] += hv.x * wv.x + hv.y * wv.y + hv.z * wv.z + hv.w * wv.w;
        }
    }
#pragma unroll
    for (int h = 0; h < 32; h++) {
        float v = acc[h];
        v += __shfl_xor_sync(0xffffffffu, v, 16);
        v += __shfl_xor_sync(0xffffffffu, v, 8);
        v += __shfl_xor_sync(0xffffffffu, v, 4);
        v += __shfl_xor_sync(0xffffffffu, v, 2);
        v += __shfl_xor_sync(0xffffffffu, v, 1);
        if (lane == h) out[(size_t)t * 32 + h] = v + lr_bias[h];
    }
}

// ---------------------------------------------------------------------------
// Scan kernel: one CTA per (b,h) pair, loops over 128 minibatches.
// ---------------------------------------------------------------------------
__device__ __forceinline__ float rsum16(float v)
{
    v += __shfl_xor_sync(0xffffffffu, v, 1);
    v += __shfl_xor_sync(0xffffffffu, v, 2);
    v += __shfl_xor_sync(0xffffffffu, v, 4);
    v += __shfl_xor_sync(0xffffffffu, v, 8);
    return v;
}

__global__ __launch_bounds__(256, 1) void scan_kernel(
    const float* __restrict__ Q, const float* __restrict__ K_,
    const float* __restrict__ V, const float* __restrict__ LR,
    const float* __restrict__ W1_0, const float* __restrict__ b1_0,
    const float* __restrict__ lnw, const float* __restrict__ lnb,
    const float* __restrict__ ltk, float* __restrict__ Y)
{
    const int SD = 65;
    __shared__ __align__(16) float W1[64 * 64];
    __shared__ float xq[16 * 65], xk[16 * 65], xv[16 * 65], gr[16 * 65];
    __shared__ float b1v[64], gam[64], bet[64];
    __shared__ float coef[256], evec[16], tok[16];

    int bh = blockIdx.x, b = bh >> 5, h = bh & 31;
    int tid = threadIdx.x;

    for (int i = tid; i < 4096; i += 256) W1[i] = W1_0[h * 4096 + i];
    if (tid < 64) {
        b1v[tid] = b1_0[h * 64 + tid];
        gam[tid] = lnw[h * 64 + tid];
        bet[tid] = lnb[h * 64 + tid];
    }
    if (tid < 16) tok[tid] = fmaxf(1.0f / (float)(tid + 1) + ltk[tid], 0.0f);
    __syncthreads();

    int r = tid >> 4;
    int g4 = (tid & 15) << 2;

    for (int nm = 0; nm < 128; nm++) {
        size_t base = ((size_t)b * 2048 + (size_t)nm * 16) * 2048 + (size_t)h * 64;
        for (int i = tid; i < 1024; i += 256) {
            int k = i >> 6, d = i & 63;
            size_t gi = base + (size_t)k * 2048 + d;
            xq[k * SD + d] = Q[gi];
            xk[k * SD + d] = K_[gi];
            xv[k * SD + d] = V[gi];
        }
        if (tid < 16) {
            float x = LR[((size_t)b * 2048 + (size_t)nm * 16 + tid) * 32 + h];
            evec[tid] = (1.0f / (1.0f + expf(-x))) * (1.0f / 64.0f);
        }
        __syncthreads();

        float z[4], qw[4];
#pragma unroll
        for (int t = 0; t < 4; t++) { z[t] = b1v[g4 + t]; qw[t] = b1v[g4 + t]; }
        for (int c = 0; c < 64; c++) {
            float kc = xk[r * SD + c], qc = xq[r * SD + c];
            float4 w4 = *(const float4*)&W1[c * 64 + g4];
            z[0] += kc * w4.x; z[1] += kc * w4.y; z[2] += kc * w4.z; z[3] += kc * w4.w;
            qw[0] += qc * w4.x; qw[1] += qc * w4.y; qw[2] += qc * w4.z; qw[3] += qc * w4.w;
        }

        float s = z[0] + z[1] + z[2] + z[3];
        s = rsum16(s);
        float mu = s * (1.0f / 64.0f);
        float xh[4]; float vs = 0.0f;
#pragma unroll
        for (int t = 0; t < 4; t++) { float d0 = z[t] - mu; xh[t] = d0; vs += d0 * d0; }
        vs = rsum16(vs);
        float rstd = 1.0f / sqrtf(vs * (1.0f / 64.0f) + 1e-6f);
        float gxh[4]; float s1 = 0.0f, s2 = 0.0f;
#pragma unroll
        for (int t = 0; t < 4; t++) {
            xh[t] *= rstd;
            float tgt = xv[r * SD + g4 + t] - xk[r * SD + g4 + t];
            float gm = gam[g4 + t];
            gxh[t] = (gm * xh[t] + bet[g4 + t] - tgt) * gm;
            s1 += gxh[t]; s2 += gxh[t] * xh[t];
        }
        s1 = rsum16(s1);
        s2 = rsum16(s2);
        float c1 = rstd * (1.0f / 64.0f);
#pragma unroll
        for (int t = 0; t < 4; t++)
            gr[r * SD + g4 + t] = (64.0f * gxh[t] - s1 - xh[t] * s2) * c1;
        __syncthreads();

        {
            int i = r, j = tid & 15;
            float a = 0.0f;
            for (int c = 0; c < 64; c++) a += xq[i * SD + c] * xk[j * SD + c];
            coef[i * 16 + j] = (j <= i) ? tok[i] * evec[j] * (1.0f + a) : 0.0f;
        }
        __syncthreads();

        float zb[4] = {qw[0], qw[1], qw[2], qw[3]};
        for (int j = 0; j < 16; j++) {
            float cf = coef[r * 16 + j];
            zb[0] -= cf * gr[j * SD + g4 + 0];
            zb[1] -= cf * gr[j * SD + g4 + 1];
            zb[2] -= cf * gr[j * SD + g4 + 2];
            zb[3] -= cf * gr[j * SD + g4 + 3];
        }
        float s0 = zb[0] + zb[1] + zb[2] + zb[3];
        s0 = rsum16(s0);
        float mu2 = s0 * (1.0f / 64.0f);
        float v2 = 0.0f;
#pragma unroll
        for (int t = 0; t < 4; t++) { float d0 = zb[t] - mu2; v2 += d0 * d0; }
        v2 = rsum16(v2);
        float rstd2 = rsqrtf(v2 * (1.0f / 64.0f) + 1e-6f);
        {
            float o0 = xq[r * SD + g4 + 0] + gam[g4 + 0] * ((zb[0] - mu2) * rstd2) + bet[g4 + 0];
            float o1 = xq[r * SD + g4 + 1] + gam[g4 + 1] * ((zb[1] - mu2) * rstd2) + bet[g4 + 1];
            float o2 = xq[r * SD + g4 + 2] + gam[g4 + 2] * ((zb[2] - mu2) * rstd2) + bet[g4 + 2];
            float o3 = xq[r * SD + g4 + 3] + gam[g4 + 3] * ((zb[3] - mu2) * rstd2) + bet[g4 + 3];
            *(float4*)&Y[base + (size_t)r * 2048 + g4] = make_float4(o0, o1, o2, o3);
        }
        __syncthreads();

        for (int i = tid; i < 1024; i += 256) {
            int j = i >> 6, d = i & 63;
            gr[j * SD + d] *= tok[15] * evec[j];
        }
        __syncthreads();

#pragma unroll
        for (int cc = 0; cc < 4; cc++) {
            int c = r + cc * 16;
            float4* wp = (float4*)&W1[c * 64 + g4];
            float4 w = *wp;
#pragma unroll
            for (int j = 0; j < 16; j++) {
                float xkc = xk[j * SD + c];
                w.x -= xkc * gr[j * SD + g4 + 0];
                w.y -= xkc * gr[j * SD + g4 + 1];
                w.z -= xkc * gr[j * SD + g4 + 2];
                w.w -= xkc * gr[j * SD + g4 + 3];
            }
            *wp = w;
        }
        if (tid < 64) {
            float bb = b1v[tid];
#pragma unroll
            for (int j = 0; j < 16; j++) bb -= gr[j * SD + tid];
            b1v[tid] = bb;
        }
        __syncthreads();
    }
}

// ---------------------------------------------------------------------------
// Post layernorm over HS=2048, in place on Y; output rounded to tf32 values
// (feeds the o-projection GEMM which assumes pre-rounded input).
// ---------------------------------------------------------------------------
__global__ void postln_kernel(float* __restrict__ Y,
                              const float* __restrict__ w, const float* __restrict__ b)
{
    int t = blockIdx.x;
    float* row = Y + (size_t)t * 2048;
    __shared__ float rs[8], rss[8], mv[2];
    int tid = threadIdx.x;
    float v[8]; float s = 0.0f, ss = 0.0f;
#pragma unroll
    for (int i = 0; i < 8; i++) {
        v[i] = row[tid + i * 256];
        s += v[i]; ss += v[i] * v[i];
    }
#pragma unroll
    for (int m = 16; m >= 1; m >>= 1) {
        s  += __shfl_xor_sync(0xffffffffu, s, m);
        ss += __shfl_xor_sync(0xffffffffu, ss, m);
    }
    if ((tid & 31) == 0) { rs[tid >> 5] = s; rss[tid >> 5] = ss; }
    __syncthreads();
    if (tid == 0) {
        float a = 0.0f, c = 0.0f;
        for (int i = 0; i < 8; i++) { a += rs[i]; c += rss[i]; }
        float mu = a * (1.0f / 2048.0f);
        float var = c * (1.0f / 2048.0f) - mu * mu;
        mv[0] = mu; mv[1] = rsqrtf(var + 1e-6f);
    }
    __syncthreads();
    float mu = mv[0], rstd = mv[1];
#pragma unroll
    for (int i = 0; i < 8; i++) {
        int d = tid + i * 256;
        float o = w[d] * ((v[i] - mu) * rstd) + b[d];
        row[d] = __uint_as_float(f2tf(o));
    }
}

// ---------------------------------------------------------------------------
extern "C" void kernel_launch(void* const* d_in, const int* in_sizes, int n_in,
                              void* d_out, int out_size)
{
    const float* hidden = (const float*)d_in[0];
    const float* q_w  = (const float*)d_in[2];
    const float* k_w  = (const float*)d_in[3];
    const float* v_w  = (const float*)d_in[4];
    const float* o_w  = (const float*)d_in[5];
    const float* W1_0 = (const float*)d_in[6];
    const float* b1_0 = (const float*)d_in[7];
    const float* lnw  = (const float*)d_in[8];
    const float* lnb  = (const float*)d_in[9];
    const float* lr_w = (const float*)d_in[10];
    const float* lr_b = (const float*)d_in[11];
    const float* ltk  = (const float*)d_in[12];
    const float* pnw  = (const float*)d_in[13];
    const float* pnb  = (const float*)d_in[14];
    float* out = (float*)d_out;

    float *Qp, *Kp, *Vp, *Yp, *LRp, *Hr, *Wq, *Wk, *Wv, *Wo;
    cudaGetSymbolAddress((void**)&Qp,  g_Q);
    cudaGetSymbolAddress((void**)&Kp,  g_K);
    cudaGetSymbolAddress((void**)&Vp,  g_V);
    cudaGetSymbolAddress((void**)&Yp,  g_Y);
    cudaGetSymbolAddress((void**)&LRp, g_LR);
    cudaGetSymbolAddress((void**)&Hr,  g_Hr);
    cudaGetSymbolAddress((void**)&Wq,  g_Wq);
    cudaGetSymbolAddress((void**)&Wk,  g_Wk);
    cudaGetSymbolAddress((void**)&Wv,  g_Wv);
    cudaGetSymbolAddress((void**)&Wo,  g_Wo);

    cudaFuncSetAttribute(gemm_tf32_nt, cudaFuncAttributeMaxDynamicSharedMemorySize, GEMM_SMEM);

    // pre-round all GEMM inputs to tf32 values (bit-identical to in-loop cvt)
    round_tf32_kernel<<<16384, 256>>>(hidden, Hr, 8192 * 2048 / 4);
    round_tf32_kernel<<<4096, 256>>>(q_w, Wq, 2048 * 2048 / 4);
    round_tf32_kernel<<<4096, 256>>>(k_w, Wk, 2048 * 2048 / 4);
    round_tf32_kernel<<<4096, 256>>>(v_w, Wv, 2048 * 2048 / 4);
    round_tf32_kernel<<<4096, 256>>>(o_w, Wo, 2048 * 2048 / 4);

    dim3 gg(2048 / 128, 8192 / 128);
    gemm_tf32_nt<<<gg, 256, GEMM_SMEM>>>(Hr, Wq, Qp);
    gemm_tf32_nt<<<gg, 256, GEMM_SMEM>>>(Hr, Wk, Kp);
    gemm_tf32_nt<<<gg, 256, GEMM_SMEM>>>(Hr, Wv, Vp);
    lr_kernel<<<1024, 256>>>(hidden, lr_w, lr_b, LRp);
    scan_kernel<<<128, 256>>>(Qp, Kp, Vp, LRp, W1_0, b1_0, lnw, lnb, ltk, Yp);
    postln_kernel<<<8192, 256>>>(Yp, pnw, pnb);
    gemm_tf32_nt<<<gg, 256, GEMM_SMEM>>>(Yp, Wo, out);
}